// round 7
// baseline (speedup 1.0000x reference)
#include <cuda_runtime.h>
#include <stdint.h>
#include <math.h>

#define HH 96
#define WW 96
#define NPIX 9216
#define NB 32
#define NS 50

// ---------------- scratch ----------------
__device__ int      g_sel_idx[NB * 2 * NS];   // [img][cls][50] rank order
__device__ float    g_trp[NB * 50 * 6 * 2];   // negated standardized, pair-packed
__device__ float    g_ms[NB * 10];            // mean[5], std[5]
__device__ float4   g_clip4[NB * NPIX];       // img_p (clipped) per pixel
__device__ uint32_t g_cmax_u[NB * 3];         // per-channel max (float-as-uint, idempotent)
__device__ uint32_t g_rv[NB * NPIX];          // ((bits>>9)+1) | (bg?1<<24:0)
__device__ uint32_t g_hist[NB * 2 * 256];     // per (img,cls) bin counts

// ---------------- threefry2x32 ----------------
__device__ __forceinline__ void tf2x32(uint32_t k0, uint32_t k1,
                                       uint32_t c0, uint32_t c1,
                                       uint32_t& o0, uint32_t& o1) {
    uint32_t ks2 = k0 ^ k1 ^ 0x1BD11BDAu;
    uint32_t x0 = c0 + k0, x1 = c1 + k1;
#define TF_RND(r) { x0 += x1; x1 = (x1 << (r)) | (x1 >> (32 - (r))); x1 ^= x0; }
    TF_RND(13) TF_RND(15) TF_RND(26) TF_RND(6)   x0 += k1;  x1 += ks2 + 1u;
    TF_RND(17) TF_RND(29) TF_RND(16) TF_RND(24)  x0 += ks2; x1 += k0 + 2u;
    TF_RND(13) TF_RND(15) TF_RND(26) TF_RND(6)   x0 += k0;  x1 += k1 + 3u;
    TF_RND(17) TF_RND(29) TF_RND(16) TF_RND(24)  x0 += k1;  x1 += ks2 + 4u;
    TF_RND(13) TF_RND(15) TF_RND(26) TF_RND(6)   x0 += ks2; x1 += k0 + 5u;
#undef TF_RND
    o0 = x0; o1 = x1;
}

__device__ __forceinline__ void image_keys(int b, uint32_t& f0, uint32_t& f1,
                                           uint32_t& g0, uint32_t& g1) {
    uint32_t kb0, kb1;
    tf2x32(0u, 42u, 0u, (uint32_t)b, kb0, kb1);
    tf2x32(kb0, kb1, 0u, 0u, f0, f1);
    tf2x32(kb0, kb1, 0u, 1u, g0, g1);
}

__device__ __forceinline__ uint32_t rbits(uint32_t k0, uint32_t k1, int p) {
    uint32_t o0, o1;
    tf2x32(k0, k1, 0u, (uint32_t)p, o0, o1);
    return o0 ^ o1;
}

__device__ __forceinline__ float clip255(float x) {
    return fminf(fmaxf(x / 255.0f, 0.0f), 1.0f);
}

// ---------------- packed f32x2 helpers ----------------
__device__ __forceinline__ uint64_t pk2(float lo, float hi) {
    uint64_t r; asm("mov.b64 %0, {%1, %2};" : "=l"(r) : "f"(lo), "f"(hi)); return r;
}
__device__ __forceinline__ void unpk2(float& lo, float& hi, uint64_t v) {
    asm("mov.b64 {%0, %1}, %2;" : "=f"(lo), "=f"(hi) : "l"(v));
}
__device__ __forceinline__ uint64_t add2(uint64_t a, uint64_t b) {
    uint64_t r; asm("add.rn.f32x2 %0, %1, %2;" : "=l"(r) : "l"(a), "l"(b)); return r;
}
__device__ __forceinline__ uint64_t mul2(uint64_t a, uint64_t b) {
    uint64_t r; asm("mul.rn.f32x2 %0, %1, %2;" : "=l"(r) : "l"(a), "l"(b)); return r;
}
__device__ __forceinline__ uint64_t fma2(uint64_t a, uint64_t b, uint64_t c) {
    uint64_t r; asm("fma.rn.f32x2 %0, %1, %2, %3;" : "=l"(r) : "l"(a), "l"(b), "l"(c)); return r;
}

// ============ kernel 1: clip image once + per-channel max + zero hist ============
// grid 288 (9 blocks per image), 1024 threads
__global__ void __launch_bounds__(1024) k_clip(const float* __restrict__ img) {
    __shared__ uint32_t smx[3];
    int blk = blockIdx.x, t = threadIdx.x;
    int b = blk / 9, p = (blk % 9) * 1024 + t;

    if (blk < 16) g_hist[blk * 1024 + t] = 0u;   // 16384 = NB*2*256
    if (t < 3) smx[t] = 0u;
    __syncthreads();

    const float* px = img + ((size_t)b * NPIX + p) * 3;
    float c0 = clip255(px[0]);
    float c1 = clip255(px[1]);
    float c2 = clip255(px[2]);
    g_clip4[(size_t)b * NPIX + p] = make_float4(c0, c1, c2, 0.0f);

    uint32_t r0 = __reduce_max_sync(0xFFFFFFFFu, __float_as_uint(c0));
    uint32_t r1 = __reduce_max_sync(0xFFFFFFFFu, __float_as_uint(c1));
    uint32_t r2 = __reduce_max_sync(0xFFFFFFFFu, __float_as_uint(c2));
    if ((t & 31) == 0) {
        atomicMax(&smx[0], r0); atomicMax(&smx[1], r1); atomicMax(&smx[2], r2);
    }
    __syncthreads();
    if (t < 3) atomicMax(&g_cmax_u[b * 3 + t], smx[t]);   // idempotent across replays
}

// ============ kernel 2: validity + 1 threefry/pixel + hist ============
// grid 288, 1024 threads
__global__ void __launch_bounds__(1024) k_bits() {
    __shared__ uint32_t keys[4];
    __shared__ float cmx[3];
    int blk = blockIdx.x, t = threadIdx.x;
    int b = blk / 9, p = (blk % 9) * 1024 + t;

    if (t == 0) {
        uint32_t f0, f1, g0, g1;
        image_keys(b, f0, f1, g0, g1);
        keys[0] = f0; keys[1] = f1; keys[2] = g0; keys[3] = g1;
    }
    if (t < 3) cmx[t] = __uint_as_float(g_cmax_u[b * 3 + t]);
    __syncthreads();

    float4 c = g_clip4[(size_t)b * NPIX + p];
    float v0 = c.x / cmx[0];
    float v1 = c.y / cmx[1];
    float v2 = c.z / cmx[2];
    bool fg = (v0 > 0.0f && v0 < 0.6f) || (v1 > 0.0f && v1 < 0.6f) || (v2 > 0.0f && v2 < 0.6f);

    uint32_t k0 = fg ? keys[0] : keys[2];
    uint32_t k1 = fg ? keys[1] : keys[3];
    uint32_t bits = rbits(k0, k1, p);
    g_rv[(size_t)b * NPIX + p] = ((bits >> 9) + 1u) | (fg ? 0u : (1u << 24));
    atomicAdd(&g_hist[(b * 2 + (fg ? 0 : 1)) * 256 + (bits >> 24)], 1u);
}

// ============ kernel 3: pivot + collect + rank (per image,cls) ============
__global__ void __launch_bounds__(1024) k_pick() {
    __shared__ uint32_t shist[256];
    __shared__ unsigned long long cand[512];
    __shared__ int s_cnt, s_pivot;

    int blk = blockIdx.x, b = blk >> 1, cls = blk & 1;
    int t = threadIdx.x;

    if (t < 256) shist[t] = g_hist[blk * 256 + t];
    if (t == 0) s_cnt = 0;
    __syncthreads();

    // pivot: warp-parallel suffix scan over 256 bins
    if (t < 32) {
        int csum = 0;
        #pragma unroll
        for (int i = 0; i < 8; i++) csum += (int)shist[t * 8 + i];
        int suf = csum;
        #pragma unroll
        for (int o = 1; o < 32; o <<= 1) {
            int v = __shfl_down_sync(0xFFFFFFFFu, suf, o);
            if (t + o < 32) suf += v;
        }
        unsigned ball = __ballot_sync(0xFFFFFFFFu, suf >= NS);
        if (ball) {
            int L = 31 - __clz(ball);
            if (t == L) {
                int acc = suf - csum;
                int pv = 8 * L;
                for (int bin = 8 * L + 7; bin >= 8 * L; bin--) {
                    acc += (int)shist[bin];
                    if (acc >= NS) { pv = bin; break; }
                }
                s_pivot = pv;
            }
        } else if (t == 0) s_pivot = -1;
    }
    __syncthreads();

    int pivot = s_pivot;
    #pragma unroll
    for (int q = 0; q < 9; q++) {
        int p = t + q * 1024;
        uint32_t rv = g_rv[(size_t)b * NPIX + p];
        bool valid = (int)((rv >> 24) & 1u) == cls;
        uint32_t v = rv & 0xFFFFFFu;
        bool take;
        if (pivot >= 0) take = valid && ((int)((v - 1u) >> 15) >= pivot);
        else            take = valid || (p < 100);   // few-valid fallback
        if (take) {
            int slot = atomicAdd(&s_cnt, 1);
            if (slot < 512)
                cand[slot] = ((unsigned long long)v << 14) |
                             (unsigned long long)(NPIX - 1 - p);
        }
    }
    __syncthreads();

    // rank by all-pairs count (keys unique) -> exact lax.top_k order
    int cnt = s_cnt < 512 ? s_cnt : 512;
    if (t < cnt) {
        unsigned long long ki = cand[t];
        int rank = 0;
        for (int j = 0; j < cnt; j++) rank += (cand[j] > ki);
        if (rank < NS) {
            int p = NPIX - 1 - (int)(ki & 0x3FFFull);
            g_sel_idx[blk * NS + rank] = p;
        }
    }
}

// ============ kernel 4: train stats + packed negated train matrix ============
__global__ void __launch_bounds__(128) k_train() {
    __shared__ float fe[100 * 5];
    __shared__ float ms[10];
    int b = blockIdx.x, t = threadIdx.x;

    if (t < 100) {
        int p = (t < 50) ? g_sel_idx[(b * 2 + 0) * NS + t]
                         : g_sel_idx[(b * 2 + 1) * NS + (t - 50)];
        int i = p / WW, j = p % WW;
        float4 c = g_clip4[(size_t)b * NPIX + p];
        fe[t * 5 + 0] = c.x / 255.0f;
        fe[t * 5 + 1] = c.y / 255.0f;
        fe[t * 5 + 2] = c.z / 255.0f;
        fe[t * 5 + 3] = ((float)i / 96.0f) * 100.0f;
        fe[t * 5 + 4] = ((float)j / 96.0f) * 100.0f;
    }
    __syncthreads();
    if (t < 5) {
        float s = 0.0f;
        for (int r = 0; r < 100; r++) s += fe[r * 5 + t];
        float m = s / 100.0f;
        float v = 0.0f;
        for (int r = 0; r < 100; r++) { float d = fe[r * 5 + t] - m; v += d * d; }
        ms[t] = m;
        ms[5 + t] = sqrtf(v / 100.0f);
    }
    __syncthreads();
    if (t < 100) {
        int m = t >> 1, h = t & 1;
        float* dst = g_trp + ((size_t)b * 50 + m) * 12;
        #pragma unroll
        for (int f = 0; f < 5; f++)
            dst[f * 2 + h] = -((fe[t * 5 + f] - ms[f]) / ms[5 + f]);
        dst[5 * 2 + h] = 0.0f;
    }
    if (t < 10) g_ms[b * 10 + t] = ms[t];
}

// ============ kernel 5: KNN segmentation + masking (packed f32x2) ============
__global__ void __launch_bounds__(256) k_seg(float* __restrict__ out) {
    __shared__ ulonglong2 stq[150];  // 50 pairs x 3 ulonglong2 = 600 floats
    __shared__ float ms[10];
    int b = blockIdx.y, t = threadIdx.x;

    if (t < 150) ((float4*)stq)[t] = ((const float4*)(g_trp + (size_t)b * 600))[t];
    if (t < 10) ms[t] = g_ms[b * 10 + t];
    __syncthreads();

    int p = blockIdx.x * 256 + t;
    float4 c = g_clip4[(size_t)b * NPIX + p];
    int i = p / WW, j = p % WW;

    float ts0 = (c.x / 255.0f - ms[0]) / ms[5];
    float ts1 = (c.y / 255.0f - ms[1]) / ms[6];
    float ts2 = (c.z / 255.0f - ms[2]) / ms[7];
    float ts3 = (((float)i / 96.0f) * 100.0f - ms[3]) / ms[8];
    float ts4 = (((float)j / 96.0f) * 100.0f - ms[4]) / ms[9];

    uint64_t tp0 = pk2(ts0, ts0), tp1 = pk2(ts1, ts1), tp2 = pk2(ts2, ts2);
    uint64_t tp3 = pk2(ts3, ts3), tp4 = pk2(ts4, ts4);

    const float INF = __int_as_float(0x7F800000);
    float a1 = INF, a2 = INF;                       // 2 smallest fg d2
    float b1 = INF, b2 = INF, b3 = INF, b4 = INF;   // 4 smallest bg d2

    #pragma unroll 5
    for (int m = 0; m < 25; m++) {                  // fg pairs
        ulonglong2 q0 = stq[3 * m], q1 = stq[3 * m + 1], q2 = stq[3 * m + 2];
        uint64_t d0 = add2(tp0, q0.x), d1 = add2(tp1, q0.y);
        uint64_t d2_ = add2(tp2, q1.x), d3 = add2(tp3, q1.y);
        uint64_t d4 = add2(tp4, q2.x);
        uint64_t s = mul2(d0, d0);
        s = fma2(d1, d1, s); s = fma2(d2_, d2_, s);
        s = fma2(d3, d3, s); s = fma2(d4, d4, s);
        float lo, hi; unpk2(lo, hi, s);
        float u = fmaxf(lo, a1); a2 = fminf(u, a2); a1 = fminf(lo, a1);
        u = fmaxf(hi, a1);       a2 = fminf(u, a2); a1 = fminf(hi, a1);
    }
    #pragma unroll 5
    for (int m = 25; m < 50; m++) {                 // bg pairs
        ulonglong2 q0 = stq[3 * m], q1 = stq[3 * m + 1], q2 = stq[3 * m + 2];
        uint64_t d0 = add2(tp0, q0.x), d1 = add2(tp1, q0.y);
        uint64_t d2_ = add2(tp2, q1.x), d3 = add2(tp3, q1.y);
        uint64_t d4 = add2(tp4, q2.x);
        uint64_t s = mul2(d0, d0);
        s = fma2(d1, d1, s); s = fma2(d2_, d2_, s);
        s = fma2(d3, d3, s); s = fma2(d4, d4, s);
        float lo, hi; unpk2(lo, hi, s);
        float u3 = fmaxf(lo, b3), u2 = fmaxf(lo, b2), u1 = fmaxf(lo, b1);
        b4 = fminf(u3, b4); b3 = fminf(u2, b3); b2 = fminf(u1, b2); b1 = fminf(lo, b1);
        u3 = fmaxf(hi, b3); u2 = fmaxf(hi, b2); u1 = fmaxf(hi, b1);
        b4 = fminf(u3, b4); b3 = fminf(u2, b3); b2 = fminf(u1, b2); b1 = fminf(hi, b1);
    }

    // seg = 1 iff 2nd-min fg sqrt-dist <= 4th-min bg sqrt-dist
    bool seg = (sqrtf(a2) <= sqrtf(b4));
    float* o = out + ((size_t)b * NPIX + p) * 3;
    if (seg) { o[0] = c.x; o[1] = c.y; o[2] = c.z; }
    else     { o[0] = 0.0f; o[1] = 0.0f; o[2] = 0.0f; }
}

// ---------------- launch ----------------
extern "C" void kernel_launch(void* const* d_in, const int* in_sizes, int n_in,
                              void* d_out, int out_size) {
    const float* img = (const float*)d_in[0];
    float* out = (float*)d_out;
    k_clip<<<288, 1024>>>(img);
    k_bits<<<288, 1024>>>();
    k_pick<<<NB * 2, 1024>>>();
    k_train<<<NB, 128>>>();
    k_seg<<<dim3(NPIX / 256, NB), 256>>>(out);
}

// round 8
// speedup vs baseline: 1.0657x; 1.0657x over previous
#include <cuda_runtime.h>
#include <stdint.h>
#include <math.h>

#define HH 96
#define WW 96
#define NPIX 9216
#define NB 32
#define NS 50

// ---------------- scratch ----------------
__device__ float    g_trp[NB * 50 * 6 * 2];   // negated standardized, pair-packed
__device__ float    g_ms[NB * 10];            // mean[5], std[5]
__device__ float4   g_clip4[NB * NPIX];       // img_p (clipped) per pixel
__device__ uint32_t g_rv[NB * NPIX];          // ((bits>>9)+1) | (bg?1<<24:0)

// ---------------- threefry2x32 ----------------
__device__ __forceinline__ void tf2x32(uint32_t k0, uint32_t k1,
                                       uint32_t c0, uint32_t c1,
                                       uint32_t& o0, uint32_t& o1) {
    uint32_t ks2 = k0 ^ k1 ^ 0x1BD11BDAu;
    uint32_t x0 = c0 + k0, x1 = c1 + k1;
#define TF_RND(r) { x0 += x1; x1 = (x1 << (r)) | (x1 >> (32 - (r))); x1 ^= x0; }
    TF_RND(13) TF_RND(15) TF_RND(26) TF_RND(6)   x0 += k1;  x1 += ks2 + 1u;
    TF_RND(17) TF_RND(29) TF_RND(16) TF_RND(24)  x0 += ks2; x1 += k0 + 2u;
    TF_RND(13) TF_RND(15) TF_RND(26) TF_RND(6)   x0 += k0;  x1 += k1 + 3u;
    TF_RND(17) TF_RND(29) TF_RND(16) TF_RND(24)  x0 += k1;  x1 += ks2 + 4u;
    TF_RND(13) TF_RND(15) TF_RND(26) TF_RND(6)   x0 += ks2; x1 += k0 + 5u;
#undef TF_RND
    o0 = x0; o1 = x1;
}

__device__ __forceinline__ void image_keys(int b, uint32_t& f0, uint32_t& f1,
                                           uint32_t& g0, uint32_t& g1) {
    uint32_t kb0, kb1;
    tf2x32(0u, 42u, 0u, (uint32_t)b, kb0, kb1);
    tf2x32(kb0, kb1, 0u, 0u, f0, f1);
    tf2x32(kb0, kb1, 0u, 1u, g0, g1);
}

__device__ __forceinline__ uint32_t rbits(uint32_t k0, uint32_t k1, int p) {
    uint32_t o0, o1;
    tf2x32(k0, k1, 0u, (uint32_t)p, o0, o1);
    return o0 ^ o1;
}

__device__ __forceinline__ float clip255(float x) {
    return fminf(fmaxf(x / 255.0f, 0.0f), 1.0f);
}

// ---------------- packed f32x2 helpers ----------------
__device__ __forceinline__ uint64_t pk2(float lo, float hi) {
    uint64_t r; asm("mov.b64 %0, {%1, %2};" : "=l"(r) : "f"(lo), "f"(hi)); return r;
}
__device__ __forceinline__ void unpk2(float& lo, float& hi, uint64_t v) {
    asm("mov.b64 {%0, %1}, %2;" : "=f"(lo), "=f"(hi) : "l"(v));
}
__device__ __forceinline__ uint64_t add2(uint64_t a, uint64_t b) {
    uint64_t r; asm("add.rn.f32x2 %0, %1, %2;" : "=l"(r) : "l"(a), "l"(b)); return r;
}
__device__ __forceinline__ uint64_t mul2(uint64_t a, uint64_t b) {
    uint64_t r; asm("mul.rn.f32x2 %0, %1, %2;" : "=l"(r) : "l"(a), "l"(b)); return r;
}
__device__ __forceinline__ uint64_t fma2(uint64_t a, uint64_t b, uint64_t c) {
    uint64_t r; asm("fma.rn.f32x2 %0, %1, %2, %3;" : "=l"(r) : "l"(a), "l"(b), "l"(c)); return r;
}

// ============ kernel 1: everything up to the train matrix, 1 block/image ============
__global__ void __launch_bounds__(1024) k_prep(const float* __restrict__ img) {
    __shared__ uint32_t hist[512];                 // [cls][256]
    __shared__ unsigned long long cand[2][512];
    __shared__ int cnts[2], pivots[2];
    __shared__ uint32_t keys4[4], cmu[3];
    __shared__ float cmx[3];
    __shared__ float fe[500];
    __shared__ int sel[100];
    __shared__ float ms[10];

    int b = blockIdx.x, t = threadIdx.x;
    int lane = t & 31, wid = t >> 5;
    const float* base = img + (size_t)b * NPIX * 3;

    if (t == 0) {
        uint32_t f0, f1, g0, g1;
        image_keys(b, f0, f1, g0, g1);
        keys4[0] = f0; keys4[1] = f1; keys4[2] = g0; keys4[3] = g1;
        cnts[0] = 0; cnts[1] = 0;
    }
    if (t < 512) hist[t] = 0u;
    if (t < 3) cmu[t] = 0u;
    __syncthreads();

    // pass 1: clip + store + channel max
    float m0 = 0.0f, m1 = 0.0f, m2 = 0.0f;
    #pragma unroll
    for (int q = 0; q < 9; q++) {
        int p = q * 1024 + t;
        const float* px = base + (size_t)p * 3;
        float c0 = clip255(px[0]);
        float c1 = clip255(px[1]);
        float c2 = clip255(px[2]);
        g_clip4[(size_t)b * NPIX + p] = make_float4(c0, c1, c2, 0.0f);
        m0 = fmaxf(m0, c0); m1 = fmaxf(m1, c1); m2 = fmaxf(m2, c2);
    }
    uint32_t r0 = __reduce_max_sync(0xFFFFFFFFu, __float_as_uint(m0));
    uint32_t r1 = __reduce_max_sync(0xFFFFFFFFu, __float_as_uint(m1));
    uint32_t r2 = __reduce_max_sync(0xFFFFFFFFu, __float_as_uint(m2));
    if (lane == 0) {
        atomicMax(&cmu[0], r0); atomicMax(&cmu[1], r1); atomicMax(&cmu[2], r2);
    }
    __syncthreads();
    if (t < 3) cmx[t] = __uint_as_float(cmu[t]);
    __syncthreads();

    // pass 2: validity + 1 threefry/pixel + hist
    float c0m = cmx[0], c1m = cmx[1], c2m = cmx[2];
    uint32_t kf0 = keys4[0], kf1 = keys4[1], kg0 = keys4[2], kg1 = keys4[3];
    #pragma unroll
    for (int q = 0; q < 9; q++) {
        int p = q * 1024 + t;
        float4 c = g_clip4[(size_t)b * NPIX + p];
        float v0 = c.x / c0m;
        float v1 = c.y / c1m;
        float v2 = c.z / c2m;
        bool fg = (v0 > 0.0f && v0 < 0.6f) || (v1 > 0.0f && v1 < 0.6f) || (v2 > 0.0f && v2 < 0.6f);
        uint32_t bits = rbits(fg ? kf0 : kg0, fg ? kf1 : kg1, p);
        g_rv[(size_t)b * NPIX + p] = ((bits >> 9) + 1u) | (fg ? 0u : (1u << 24));
        atomicAdd(&hist[(fg ? 0 : 256) + (bits >> 24)], 1u);
    }
    __syncthreads();

    // pivots: warp 0 -> fg, warp 1 -> bg
    if (wid < 2) {
        const uint32_t* sh = hist + wid * 256;
        int csum = 0;
        #pragma unroll
        for (int i = 0; i < 8; i++) csum += (int)sh[lane * 8 + i];
        int suf = csum;
        #pragma unroll
        for (int o = 1; o < 32; o <<= 1) {
            int v = __shfl_down_sync(0xFFFFFFFFu, suf, o);
            if (lane + o < 32) suf += v;
        }
        unsigned ball = __ballot_sync(0xFFFFFFFFu, suf >= NS);
        if (ball) {
            int L = 31 - __clz(ball);
            if (lane == L) {
                int acc = suf - csum;
                int pv = 8 * L;
                for (int bin = 8 * L + 7; bin >= 8 * L; bin--) {
                    acc += (int)sh[bin];
                    if (acc >= NS) { pv = bin; break; }
                }
                pivots[wid] = pv;
            }
        } else if (lane == 0) pivots[wid] = -1;
    }
    __syncthreads();

    // collect candidates (both classes)
    int pv0 = pivots[0], pv1 = pivots[1];
    #pragma unroll
    for (int q = 0; q < 9; q++) {
        int p = q * 1024 + t;
        uint32_t rv = g_rv[(size_t)b * NPIX + p];
        int clsv = (int)(rv >> 24);
        uint32_t v = rv & 0xFFFFFFu;
        int pvo = clsv ? pv1 : pv0;
        // own class
        bool take = (pvo >= 0) ? ((int)((v - 1u) >> 15) >= pvo) : true;
        if (take) {
            int slot = atomicAdd(&cnts[clsv], 1);
            if (slot < 512)
                cand[clsv][slot] = ((unsigned long long)v << 14) |
                                   (unsigned long long)(NPIX - 1 - p);
        }
        // other class fallback (score -1 -> v=0, index-ordered)
        int o = 1 - clsv;
        if (((o ? pv1 : pv0) < 0) && p < 100) {
            int slot = atomicAdd(&cnts[o], 1);
            if (slot < 512)
                cand[o][slot] = (unsigned long long)(NPIX - 1 - p);
        }
    }
    __syncthreads();

    // rank: threads 0-511 fg, 512-1023 bg (keys unique -> exact top_k order)
    {
        int cls = t >> 9, i = t & 511;
        int cnt = cnts[cls] < 512 ? cnts[cls] : 512;
        if (i < cnt) {
            unsigned long long ki = cand[cls][i];
            int rank = 0;
            for (int j = 0; j < cnt; j++) rank += (cand[cls][j] > ki);
            if (rank < NS)
                sel[cls * NS + rank] = NPIX - 1 - (int)(ki & 0x3FFFull);
        }
    }
    __syncthreads();

    // train features + stats + packed negated output
    if (t < 100) {
        int p = sel[t];
        int i = p / WW, j = p % WW;
        float4 c = g_clip4[(size_t)b * NPIX + p];
        fe[t * 5 + 0] = c.x / 255.0f;
        fe[t * 5 + 1] = c.y / 255.0f;
        fe[t * 5 + 2] = c.z / 255.0f;
        fe[t * 5 + 3] = ((float)i / 96.0f) * 100.0f;
        fe[t * 5 + 4] = ((float)j / 96.0f) * 100.0f;
    }
    __syncthreads();
    if (t < 5) {
        float s = 0.0f;
        for (int r = 0; r < 100; r++) s += fe[r * 5 + t];
        float m = s / 100.0f;
        float v = 0.0f;
        for (int r = 0; r < 100; r++) { float d = fe[r * 5 + t] - m; v += d * d; }
        ms[t] = m;
        ms[5 + t] = sqrtf(v / 100.0f);
    }
    __syncthreads();
    if (t < 100) {
        int m = t >> 1, h = t & 1;
        float* dst = g_trp + ((size_t)b * 50 + m) * 12;
        #pragma unroll
        for (int f = 0; f < 5; f++)
            dst[f * 2 + h] = -((fe[t * 5 + f] - ms[f]) / ms[5 + f]);
        dst[5 * 2 + h] = 0.0f;
    }
    if (t < 10) g_ms[b * 10 + t] = ms[t];
}

// ============ kernel 2: KNN segmentation + masking (packed f32x2) ============
__global__ void __launch_bounds__(1024) k_seg(float* __restrict__ out) {
    __shared__ ulonglong2 stq[150];  // 50 pairs x 3 ulonglong2 = 600 floats
    __shared__ float ms[10];
    int b = blockIdx.y, t = threadIdx.x;

    if (t < 150) ((float4*)stq)[t] = ((const float4*)(g_trp + (size_t)b * 600))[t];
    if (t < 10) ms[t] = g_ms[b * 10 + t];
    __syncthreads();

    int p = blockIdx.x * 1024 + t;
    float4 c = g_clip4[(size_t)b * NPIX + p];
    int i = p / WW, j = p % WW;

    float ts0 = (c.x / 255.0f - ms[0]) / ms[5];
    float ts1 = (c.y / 255.0f - ms[1]) / ms[6];
    float ts2 = (c.z / 255.0f - ms[2]) / ms[7];
    float ts3 = (((float)i / 96.0f) * 100.0f - ms[3]) / ms[8];
    float ts4 = (((float)j / 96.0f) * 100.0f - ms[4]) / ms[9];

    uint64_t tp0 = pk2(ts0, ts0), tp1 = pk2(ts1, ts1), tp2 = pk2(ts2, ts2);
    uint64_t tp3 = pk2(ts3, ts3), tp4 = pk2(ts4, ts4);

    const float INF = __int_as_float(0x7F800000);
    float a1 = INF, a2 = INF;                       // 2 smallest fg d2
    float b1 = INF, b2 = INF, b3 = INF, b4 = INF;   // 4 smallest bg d2

    #pragma unroll 5
    for (int m = 0; m < 25; m++) {                  // fg pairs
        ulonglong2 q0 = stq[3 * m], q1 = stq[3 * m + 1], q2 = stq[3 * m + 2];
        uint64_t d0 = add2(tp0, q0.x), d1 = add2(tp1, q0.y);
        uint64_t d2_ = add2(tp2, q1.x), d3 = add2(tp3, q1.y);
        uint64_t d4 = add2(tp4, q2.x);
        uint64_t s = mul2(d0, d0);
        s = fma2(d1, d1, s); s = fma2(d2_, d2_, s);
        s = fma2(d3, d3, s); s = fma2(d4, d4, s);
        float lo, hi; unpk2(lo, hi, s);
        float u = fmaxf(lo, a1); a2 = fminf(u, a2); a1 = fminf(lo, a1);
        u = fmaxf(hi, a1);       a2 = fminf(u, a2); a1 = fminf(hi, a1);
    }
    #pragma unroll 5
    for (int m = 25; m < 50; m++) {                 // bg pairs
        ulonglong2 q0 = stq[3 * m], q1 = stq[3 * m + 1], q2 = stq[3 * m + 2];
        uint64_t d0 = add2(tp0, q0.x), d1 = add2(tp1, q0.y);
        uint64_t d2_ = add2(tp2, q1.x), d3 = add2(tp3, q1.y);
        uint64_t d4 = add2(tp4, q2.x);
        uint64_t s = mul2(d0, d0);
        s = fma2(d1, d1, s); s = fma2(d2_, d2_, s);
        s = fma2(d3, d3, s); s = fma2(d4, d4, s);
        float lo, hi; unpk2(lo, hi, s);
        float u3 = fmaxf(lo, b3), u2 = fmaxf(lo, b2), u1 = fmaxf(lo, b1);
        b4 = fminf(u3, b4); b3 = fminf(u2, b3); b2 = fminf(u1, b2); b1 = fminf(lo, b1);
        u3 = fmaxf(hi, b3); u2 = fmaxf(hi, b2); u1 = fmaxf(hi, b1);
        b4 = fminf(u3, b4); b3 = fminf(u2, b3); b2 = fminf(u1, b2); b1 = fminf(hi, b1);
    }

    // seg = 1 iff 2nd-min fg sqrt-dist <= 4th-min bg sqrt-dist
    bool seg = (sqrtf(a2) <= sqrtf(b4));
    float* o = out + ((size_t)b * NPIX + p) * 3;
    if (seg) { o[0] = c.x; o[1] = c.y; o[2] = c.z; }
    else     { o[0] = 0.0f; o[1] = 0.0f; o[2] = 0.0f; }
}

// ---------------- launch ----------------
extern "C" void kernel_launch(void* const* d_in, const int* in_sizes, int n_in,
                              void* d_out, int out_size) {
    const float* img = (const float*)d_in[0];
    float* out = (float*)d_out;
    k_prep<<<NB, 1024>>>(img);
    k_seg<<<dim3(9, NB), 1024>>>(out);
}